// round 5
// baseline (speedup 1.0000x reference)
#include <cuda_runtime.h>

#define BB 2
#define NN 16384
#define SS 4096
#define KSAMP 32
#define CF 64
#define D1 64
#define D2 64
#define D3 128

typedef unsigned long long u64;

// weights in constant memory (warp-uniform access -> uniform/const path)
__constant__ __align__(16) float cW1[3 * 64];
__constant__ __align__(16) float cW2[64 * 64];    // [c][d]
__constant__ __align__(16) float cB2[64];
__constant__ __align__(16) float cW3[64 * 128];   // [c][d]
__constant__ __align__(16) float cB3[128];

// scratch (__device__ globals per allocation rule)
__device__ __align__(16) float4 g_pts[BB * NN];   // x,y,z,|p|^2
__device__ __align__(16) float  g_px[BB * NN];
__device__ __align__(16) float  g_py[BB * NN];
__device__ __align__(16) float  g_pz[BB * NN];
__device__ __align__(16) float  g_F1[BB * NN * D1];
__device__ __align__(16) int    g_idx[BB * SS * KSAMP];

#define OUT_FEAT_BASE (BB * SS * 3)
#define OUT_SAMP_BASE (BB * SS * 3 + BB * D3 * SS)

// ---- packed f32x2 helpers -------------------------------------------------
__device__ __forceinline__ u64 fma2(u64 a, u64 b, u64 c) {
    u64 d;
    asm("fma.rn.f32x2 %0, %1, %2, %3;" : "=l"(d) : "l"(a), "l"(b), "l"(c));
    return d;
}
__device__ __forceinline__ u64 pack2(float lo, float hi) {
    u64 d;
    asm("mov.b64 %0, {%1, %2};" : "=l"(d) : "f"(lo), "f"(hi));
    return d;
}
__device__ __forceinline__ void unpack2(u64 v, float& lo, float& hi) {
    asm("mov.b64 {%0, %1}, %2;" : "=f"(lo), "=f"(hi) : "l"(v));
}

// ---------------------------------------------------------------------------
__global__ void prep_pts(const float* __restrict__ xyz, float* __restrict__ out) {
    int i = blockIdx.x * blockDim.x + threadIdx.x;
    if (i >= BB * NN) return;
    int b = i / NN, n = i % NN;
    float x = xyz[i * 3 + 0], y = xyz[i * 3 + 1], z = xyz[i * 3 + 2];
    float nn = x * x + y * y + z * z;
    g_pts[i] = make_float4(x, y, z, nn);
    g_px[i] = x; g_py[i] = y; g_pz[i] = z;
    if (n < SS) {
        int o = (b * SS + n) * 3;
        out[o + 0] = x; out[o + 1] = y; out[o + 2] = z;
        out[OUT_SAMP_BASE + b * SS + n] = (float)n;
    }
}

// ---------------------------------------------------------------------------
// F1[b][n][co] = b1[co] + sum_c feats[b][c][n] * W1[3+c][co]
__global__ void prep_F1(const float* __restrict__ feats, const float* __restrict__ W1,
                        const float* __restrict__ b1) {
    __shared__ float Ws[CF * D1];
    __shared__ float ft[CF][64 + 1];
    int t = threadIdx.x;
    int tile = blockIdx.x;
    int b = tile / (NN / 64);
    int n0 = (tile % (NN / 64)) * 64;

    for (int e = t; e < CF * D1; e += 256) Ws[e] = W1[(3 + e / D1) * D1 + (e % D1)];
    for (int e = t; e < CF * 64; e += 256) {
        int c = e >> 6, nl = e & 63;
        ft[c][nl] = feats[(b * CF + c) * NN + n0 + nl];
    }
    __syncthreads();

    int nl = t & 63;
    int cog = t >> 6;
    float acc[16];
#pragma unroll
    for (int j = 0; j < 16; j++) acc[j] = b1[cog * 16 + j];
    for (int c = 0; c < CF; c++) {
        float f = ft[c][nl];
        const float4* w4 = (const float4*)&Ws[c * D1 + cog * 16];
#pragma unroll
        for (int q = 0; q < 4; q++) {
            float4 w = w4[q];
            acc[q * 4 + 0] = fmaf(f, w.x, acc[q * 4 + 0]);
            acc[q * 4 + 1] = fmaf(f, w.y, acc[q * 4 + 1]);
            acc[q * 4 + 2] = fmaf(f, w.z, acc[q * 4 + 2]);
            acc[q * 4 + 3] = fmaf(f, w.w, acc[q * 4 + 3]);
        }
    }
    float4* dst = (float4*)&g_F1[(size_t)(b * NN + n0 + nl) * D1 + cog * 16];
#pragma unroll
    for (int q = 0; q < 4; q++)
        dst[q] = make_float4(acc[q * 4 + 0], acc[q * 4 + 1], acc[q * 4 + 2], acc[q * 4 + 3]);
}

// ---------------------------------------------------------------------------
__global__ void __launch_bounds__(256) ballq() {
    const float R2 = (float)(0.4 * 0.4);
    __shared__ float tx[256], ty[256], tz[256];
    int t = threadIdx.x;
    int lane = t & 31;
    int w = t >> 5;
    int cid = blockIdx.x * 8 + w;
    int b = cid / SS, s = cid % SS;
    const float* px = g_px + b * NN;
    const float* py = g_py + b * NN;
    const float* pz = g_pz + b * NN;

    float cx = px[s], cy = py[s], cz = pz[s];
    float cw = cx * cx + cy * cy + cz * cz;

    int cnt = 0, first = 0;
    for (int base = 0; base < NN; base += 256) {
        __syncthreads();
        tx[t] = px[base + t]; ty[t] = py[base + t]; tz[t] = pz[base + t];
        __syncthreads();
        if (cnt < KSAMP) {
#pragma unroll
            for (int j = 0; j < 8; j++) {
                int li = j * 32 + lane;
                float qx = tx[li], qy = ty[li], qz = tz[li];
                float dot = cx * qx + cy * qy + cz * qz;
                float qw = qx * qx + qy * qy + qz * qz;
                float d2 = (cw + qw) - 2.0f * dot;
                bool hit = d2 < R2;
                unsigned m = __ballot_sync(0xffffffffu, hit);
                if (m) {
                    if (cnt == 0) first = base + j * 32 + (__ffs(m) - 1);
                    int pos = cnt + __popc(m & ((1u << lane) - 1u));
                    if (hit && pos < KSAMP) g_idx[cid * KSAMP + pos] = base + j * 32 + lane;
                    cnt += __popc(m);
                    if (cnt >= KSAMP) break;
                }
            }
        }
        if (__syncthreads_and(cnt >= KSAMP)) break;
    }
    if (lane >= cnt) g_idx[cid * KSAMP + lane] = first;
}

// ---------------------------------------------------------------------------
// MLP: warp per centroid, lane = k-sample. Activations in warp-private smem
// rows (stride 65 -> transposed reads conflict-free). ALL smem accesses are
// scalar 32-bit (odd stride makes 64-bit accesses misaligned). Weights from
// __constant__; accumulators FFMA2-packed over d-pairs in registers.
#define MWARPS 12
#define MGRID 137
#define HST 65
#define WSM (2 * KSAMP * HST)              // 2 buffers per warp
#define MLP_SMEM (MWARPS * WSM * 4)

__global__ void __launch_bounds__(384) mlp_kernel(float* __restrict__ out) {
    extern __shared__ float sm[];
    int t = threadIdx.x, lane = t & 31, w = t >> 5;
    float* hbuf = sm + w * WSM;            // [k=32][65]
    float* sbuf = hbuf + KSAMP * HST;      // [k=32][65] scratch for max

    // per-lane W1 slice (c = 2*lane, 2*lane+1)
    float w1x0 = cW1[0 * 64 + 2 * lane], w1x1 = cW1[0 * 64 + 2 * lane + 1];
    float w1y0 = cW1[1 * 64 + 2 * lane], w1y1 = cW1[1 * 64 + 2 * lane + 1];
    float w1z0 = cW1[2 * 64 + 2 * lane], w1z1 = cW1[2 * 64 + 2 * lane + 1];

    int gw = blockIdx.x * MWARPS + w;
    for (int cid = gw; cid < BB * SS; cid += MGRID * MWARPS) {
        int b = cid >> 12;                 // / SS
        int s = cid & (SS - 1);
        const float4* ptsb = g_pts + b * NN;
        const float* F1b = g_F1 + (size_t)b * NN * D1;

        int id = g_idx[cid * KSAMP + lane];
        float4 p = ptsb[id];
        float4 cc = ptsb[s];
        float rx = p.x - cc.x, ry = p.y - cc.y, rz = p.z - cc.z;

        // phase 1: cooperative gather+compute of h1 -> hbuf[k][c] (scalar STS)
#pragma unroll 4
        for (int k = 0; k < KSAMP; k++) {
            int   idk = __shfl_sync(0xffffffffu, id, k);
            float kx  = __shfl_sync(0xffffffffu, rx, k);
            float ky  = __shfl_sync(0xffffffffu, ry, k);
            float kz  = __shfl_sync(0xffffffffu, rz, k);
            float2 f = *(const float2*)&F1b[idk * D1 + 2 * lane];  // 8B-aligned gmem
            float v0 = fmaf(kx, w1x0, f.x); v0 = fmaf(ky, w1y0, v0); v0 = fmaf(kz, w1z0, v0);
            float v1 = fmaf(kx, w1x1, f.y); v1 = fmaf(ky, w1y1, v1); v1 = fmaf(kz, w1z1, v1);
            hbuf[k * HST + 2 * lane]     = fmaxf(v0, 0.f);
            hbuf[k * HST + 2 * lane + 1] = fmaxf(v1, 0.f);
        }
        __syncwarp();

        // phase 2: h2[k][d] = relu(b2 + sum_c h1[k][c] * W2[c][d])
        {
            u64 acc[32];
#pragma unroll
            for (int q = 0; q < 32; q++) acc[q] = ((const u64*)cB2)[q];
#pragma unroll 2
            for (int c = 0; c < D1; c++) {
                float h = hbuf[lane * HST + c];
                u64 hp = pack2(h, h);
                const ulonglong2* wrow = (const ulonglong2*)&cW2[c * D2];
#pragma unroll
                for (int q = 0; q < 16; q++) {
                    ulonglong2 wv = wrow[q];
                    acc[2 * q]     = fma2(hp, wv.x, acc[2 * q]);
                    acc[2 * q + 1] = fma2(hp, wv.y, acc[2 * q + 1]);
                }
            }
            __syncwarp();                  // all lanes done reading h1
#pragma unroll
            for (int q = 0; q < 32; q++) {
                float lo, hi; unpack2(acc[q], lo, hi);
                hbuf[lane * HST + 2 * q]     = fmaxf(lo, 0.f);
                hbuf[lane * HST + 2 * q + 1] = fmaxf(hi, 0.f);
            }
            __syncwarp();
        }

        // phase 3: two d-halves of 64; max over k via smem transpose
#pragma unroll 1
        for (int half = 0; half < 2; half++) {
            u64 acc[32];
#pragma unroll
            for (int q = 0; q < 32; q++) acc[q] = ((const u64*)cB3)[half * 32 + q];
#pragma unroll 2
            for (int c = 0; c < D2; c++) {
                float h = hbuf[lane * HST + c];
                u64 hp = pack2(h, h);
                const ulonglong2* wrow = (const ulonglong2*)&cW3[c * D3 + half * 64];
#pragma unroll
                for (int q = 0; q < 16; q++) {
                    ulonglong2 wv = wrow[q];
                    acc[2 * q]     = fma2(hp, wv.x, acc[2 * q]);
                    acc[2 * q + 1] = fma2(hp, wv.y, acc[2 * q + 1]);
                }
            }
#pragma unroll
            for (int q = 0; q < 32; q++) {
                float lo, hi; unpack2(acc[q], lo, hi);
                sbuf[lane * HST + 2 * q]     = fmaxf(lo, 0.f);
                sbuf[lane * HST + 2 * q + 1] = fmaxf(hi, 0.f);
            }
            __syncwarp();
            // lane owns d = half*64 + 2*lane (+1): max over 32 k
            float m0 = 0.f, m1 = 0.f;
#pragma unroll 4
            for (int k = 0; k < KSAMP; k++) {
                m0 = fmaxf(m0, sbuf[k * HST + 2 * lane]);
                m1 = fmaxf(m1, sbuf[k * HST + 2 * lane + 1]);
            }
            {
                int d = half * 64 + 2 * lane;
                size_t ob = OUT_FEAT_BASE + (size_t)b * D3 * SS + (size_t)d * SS + s;
                out[ob] = m0;
                out[ob + SS] = m1;
            }
            __syncwarp();
        }
    }
}

// ---------------------------------------------------------------------------
extern "C" void kernel_launch(void* const* d_in, const int* in_sizes, int n_in,
                              void* d_out, int out_size) {
    const float* xyz   = (const float*)d_in[0];
    const float* feats = (const float*)d_in[1];
    const float* W1    = (const float*)d_in[2];
    const float* b1    = (const float*)d_in[3];
    const float* W2    = (const float*)d_in[4];
    const float* b2    = (const float*)d_in[5];
    const float* W3    = (const float*)d_in[6];
    const float* b3    = (const float*)d_in[7];
    float* out = (float*)d_out;
    (void)in_sizes; (void)n_in; (void)out_size;

    cudaMemcpyToSymbolAsync(cW1, W1, 3 * 64 * sizeof(float), 0, cudaMemcpyDeviceToDevice, 0);
    cudaMemcpyToSymbolAsync(cW2, W2, 64 * 64 * sizeof(float), 0, cudaMemcpyDeviceToDevice, 0);
    cudaMemcpyToSymbolAsync(cB2, b2, 64 * sizeof(float), 0, cudaMemcpyDeviceToDevice, 0);
    cudaMemcpyToSymbolAsync(cW3, W3, 64 * 128 * sizeof(float), 0, cudaMemcpyDeviceToDevice, 0);
    cudaMemcpyToSymbolAsync(cB3, b3, 128 * sizeof(float), 0, cudaMemcpyDeviceToDevice, 0);

    cudaFuncSetAttribute(mlp_kernel, cudaFuncAttributeMaxDynamicSharedMemorySize, MLP_SMEM);

    prep_pts<<<(BB * NN + 255) / 256, 256>>>(xyz, out);
    prep_F1<<<BB * NN / 64, 256>>>(feats, W1, b1);
    ballq<<<BB * SS / 8, 256>>>();
    mlp_kernel<<<MGRID, 384, MLP_SMEM>>>(out);
}